// round 5
// baseline (speedup 1.0000x reference)
#include <cuda_runtime.h>
#include <cstdint>
#include <cstddef>

// Problem constants
#define T_TOK 2048
#define DIMV  512
#define MOE   256
#define NEXP  64
#define NGRP  8
#define TOPG  4
#define TOPK  8
#define CAPE  1024
#define RSCALE 2.5f

// Expert-kernel tiling
#define TM   64            // token rows per tile
#define KC1  16            // GEMM1 k-chunk (of 512)
#define NC1  (DIMV / KC1)  // 32
#define KC2  32            // GEMM2 k-chunk (of 256)
#define NC2  (MOE / KC2)   // 8
#define TILES_PER_E (CAPE / TM)  // 16

// ---------------- device scratch (static: no allocations allowed) ------------
__device__ int   g_cnt[NEXP];
__device__ int   g_tok[NEXP * CAPE];
__device__ int   g_slot[NEXP * CAPE];
__device__ float g_wt[NEXP * CAPE];
__device__ float g_yb[(size_t)T_TOK * TOPK * DIMV];   // 33.5 MB slot-indexed outputs

// ---------------- packed f32x2 helpers (Blackwell FFMA2) --------------------
__device__ __forceinline__ unsigned long long pk2(float x, float y) {
    unsigned long long r;
    asm("mov.b64 %0, {%1, %2};" : "=l"(r) : "f"(x), "f"(y));
    return r;
}
__device__ __forceinline__ void upk2(unsigned long long v, float& x, float& y) {
    asm("mov.b64 {%0, %1}, %2;" : "=f"(x), "=f"(y) : "l"(v));
}
__device__ __forceinline__ void fma2(unsigned long long& d,
                                     unsigned long long a, unsigned long long b) {
    asm("fma.rn.f32x2 %0, %1, %2, %0;" : "+l"(d) : "l"(a), "l"(b));
}
__device__ __forceinline__ unsigned su32(const void* p) {
    return (unsigned)__cvta_generic_to_shared(p);
}
#define CP16(daddr, src) \
    asm volatile("cp.async.cg.shared.global [%0], [%1], 16;\n" :: "r"(daddr), "l"(src))
#define CP_COMMIT() asm volatile("cp.async.commit_group;\n")
#define CP_WAIT1()  asm volatile("cp.async.wait_group 1;\n")
#define CP_WAIT0()  asm volatile("cp.async.wait_group 0;\n")

// ---------------------------------------------------------------------------
__global__ void k_init() {
    if (threadIdx.x < NEXP) g_cnt[threadIdx.x] = 0;
}

// One warp per token. gate_w staged through smem in 8-row chunks so the
// 128 KB gate matrix is read through L2 once per 8 tokens per SM.
__global__ void __launch_bounds__(256) k_gate(const float* __restrict__ x,
                                              const float* __restrict__ gw,
                                              const float* __restrict__ gb) {
    __shared__ float wbuf[8 * DIMV];     // 8 expert rows
    __shared__ float sc[8][NEXP];        // sigmoid scores per warp-token
    __shared__ float sb[8][NEXP];        // biased/masked scores (scratch)
    __shared__ float gbs[NEXP];

    int tid = threadIdx.x;
    int w = tid >> 5, lane = tid & 31;
    int t = blockIdx.x * 8 + w;

    if (tid < NEXP) gbs[tid] = gb[tid];

    float xr[16];
#pragma unroll
    for (int i = 0; i < 16; i++) xr[i] = x[(size_t)t * DIMV + lane + 32 * i];

    for (int ec = 0; ec < NEXP / 8; ec++) {
        __syncthreads();
#pragma unroll
        for (int q = 0; q < 16; q++) {
            int idx = q * 256 + tid;                    // 4096 floats = 8 rows
            wbuf[idx] = gw[(size_t)(ec * 8) * DIMV + idx];
        }
        __syncthreads();
#pragma unroll
        for (int j = 0; j < 8; j++) {
            float s = 0.f;
#pragma unroll
            for (int i = 0; i < 16; i++) s += xr[i] * wbuf[j * DIMV + lane + 32 * i];
#pragma unroll
            for (int off = 16; off; off >>= 1) s += __shfl_xor_sync(0xffffffffu, s, off);
            if (lane == 0) sc[w][ec * 8 + j] = 1.f / (1.f + __expf(-s));
        }
    }
    __syncthreads();

    if (lane == 0) {
        float* scw = sc[w];
        float* sbw = sb[w];
        // group scores = sum of top-2 of (score + bias) within each group of 8
        float gs[NGRP];
        for (int g = 0; g < NGRP; g++) {
            float m1 = -1e30f, m2 = -1e30f;
            for (int j = 0; j < 8; j++) {
                float v = scw[g * 8 + j] + gbs[g * 8 + j];
                if (v > m1) { m2 = m1; m1 = v; }
                else if (v > m2) { m2 = v; }
            }
            gs[g] = m1 + m2;
        }
        // top-4 groups (first-index wins on ties, matching lax.top_k)
        unsigned allowed = 0;
        for (int p = 0; p < TOPG; p++) {
            float best = -1e30f; int bi = 0;
            for (int g = 0; g < NGRP; g++)
                if (!((allowed >> g) & 1) && gs[g] > best) { best = gs[g]; bi = g; }
            allowed |= 1u << bi;
        }
        // top-8 experts among allowed groups over (score + bias)
        for (int e = 0; e < NEXP; e++)
            sbw[e] = ((allowed >> (e >> 3)) & 1) ? scw[e] + gbs[e] : -1e30f;
        int idxs[TOPK]; float wsum = 0.f;
        for (int p = 0; p < TOPK; p++) {
            float best = -1e30f; int bi = 0;
            for (int e = 0; e < NEXP; e++)
                if (sbw[e] > best) { best = sbw[e]; bi = e; }
            idxs[p] = bi; sbw[bi] = -1e30f;
            wsum += scw[bi];                 // weights use pre-bias sigmoid scores
        }
        float inv = RSCALE / wsum;
        for (int p = 0; p < TOPK; p++) {
            int e = idxs[p];
            int pos = atomicAdd(&g_cnt[e], 1);
            if (pos < CAPE) {
                g_tok[e * CAPE + pos]  = t;
                g_slot[e * CAPE + pos] = t * TOPK + p;
                g_wt[e * CAPE + pos]   = scw[e] * inv;
            }
        }
    }
}

// Fused expert FFN: one block per (expert, 64-token tile).
// GEMM1: [64,512] @ {w1,w3}[512,256] with FFMA2 packing (w1,w3) per lane-pair,
// silu*mul -> H in smem (reusing X region), GEMM2: [64,256] @ w2[256,512],
// scaled rows scattered to the slot-indexed combine buffer.
__global__ void __launch_bounds__(256, 1)
k_expert(const float* __restrict__ x,  const float* __restrict__ w1,
         const float* __restrict__ w3, const float* __restrict__ w2) {
    extern __shared__ float sm[];
    float* Xs = sm;                    // 64*512 floats (128 KB); reused as H (64*256)
    float* WB = sm + TM * DIMV;        // 16384 floats (64 KB) weight double-buffer
    __shared__ int   tok_s[TM];
    __shared__ int   slot_s[TM];
    __shared__ float wt_s[TM];

    int e    = blockIdx.x >> 4;        // TILES_PER_E = 16
    int tile = blockIdx.x & (TILES_PER_E - 1);
    int tid  = threadIdx.x;

    int n = min(g_cnt[e], CAPE);
    int r0g = tile * TM;
    if (r0g >= n) return;              // uniform over the block
    int nr = min(TM, n - r0g);

    if (tid < TM) {
        if (tid < nr) {
            tok_s[tid]  = g_tok[e * CAPE + r0g + tid];
            slot_s[tid] = g_slot[e * CAPE + r0g + tid];
            wt_s[tid]   = g_wt[e * CAPE + r0g + tid];
        } else {
            tok_s[tid] = -1;
        }
    }
    __syncthreads();

    // Gather X rows (zeros beyond nr)
#pragma unroll
    for (int q = 0; q < 32; q++) {
        int idx = q * 256 + tid;               // < 8192 float4
        int row = idx >> 7, c4 = idx & 127;
        float4 v = make_float4(0.f, 0.f, 0.f, 0.f);
        if (row < nr) v = *(const float4*)(x + (size_t)tok_s[row] * DIMV + c4 * 4);
        *(float4*)(Xs + row * DIMV + c4 * 4) = v;
    }
    __syncthreads();

    int ty = tid >> 5, tx = tid & 31, r0 = ty * 8;

    // ---------------- GEMM1: acc[i][j] = (z1, z3) for row r0+i, col tx+32j ---
    unsigned long long acc[8][8];
#pragma unroll
    for (int i = 0; i < 8; i++)
#pragma unroll
        for (int j = 0; j < 8; j++) acc[i][j] = 0ull;

    auto load1 = [&](int c, int buf) {
        const float* b1 = w1 + ((size_t)e * DIMV + c * KC1) * MOE;
        const float* b3 = w3 + ((size_t)e * DIMV + c * KC1) * MOE;
        float* dst = WB + buf * 8192;
#pragma unroll
        for (int q = 0; q < 8; q++) {
            int idx = q * 256 + tid;           // < 2048 float4
            int mat = idx >> 10;
            int kk  = (idx >> 6) & 15;
            int m4  = idx & 63;
            const float* src = (mat ? b3 : b1) + (size_t)kk * MOE + m4 * 4;
            CP16(su32(dst + mat * 4096 + kk * MOE + m4 * 4), src);
        }
    };

    load1(0, 0);
    CP_COMMIT();
    for (int c = 0; c < NC1; c++) {
        if (c + 1 < NC1) { load1(c + 1, (c + 1) & 1); CP_COMMIT(); CP_WAIT1(); }
        else             { CP_WAIT0(); }
        __syncthreads();
        const float* W1s = WB + (c & 1) * 8192;
        const float* W3s = W1s + 4096;
#pragma unroll
        for (int kk = 0; kk < KC1; kk++) {
            int kg = c * KC1 + kk;
            unsigned long long a2[8], b2[8];
#pragma unroll
            for (int i = 0; i < 8; i++) {
                float av = Xs[(r0 + i) * DIMV + kg];     // warp-broadcast LDS
                a2[i] = pk2(av, av);
            }
#pragma unroll
            for (int j = 0; j < 8; j++)
                b2[j] = pk2(W1s[kk * MOE + tx + 32 * j], W3s[kk * MOE + tx + 32 * j]);
#pragma unroll
            for (int i = 0; i < 8; i++)
#pragma unroll
                for (int j = 0; j < 8; j++) fma2(acc[i][j], a2[i], b2[j]);
        }
        __syncthreads();                       // fence before next prefetch overwrite
    }

    // silu(z1) * z3 -> H (reuse X smem region; all X reads completed above)
    float* Hs = sm;
#pragma unroll
    for (int i = 0; i < 8; i++)
#pragma unroll
        for (int j = 0; j < 8; j++) {
            float z1, z3; upk2(acc[i][j], z1, z3);
            float h = (z1 * z3) / (1.f + __expf(-z1));
            Hs[(r0 + i) * MOE + tx + 32 * j] = h;
        }
    __syncthreads();

    // ---------------- GEMM2: Y[64,512] = H @ w2, in two 256-col halves -------
    for (int nh = 0; nh < 2; nh++) {
        unsigned long long acc2[8][4];
#pragma unroll
        for (int i = 0; i < 8; i++)
#pragma unroll
            for (int j = 0; j < 4; j++) acc2[i][j] = 0ull;

        auto load2 = [&](int c, int buf) {
            const float* b = w2 + ((size_t)e * MOE + c * KC2) * DIMV + nh * 256;
            float* dst = WB + buf * 8192;
#pragma unroll
            for (int q = 0; q < 8; q++) {
                int idx = q * 256 + tid;       // < 2048 float4
                int kk = idx >> 6;             // 0..31
                int d4 = idx & 63;
                CP16(su32(dst + kk * 256 + d4 * 4), b + (size_t)kk * DIMV + d4 * 4);
            }
        };

        load2(0, 0);
        CP_COMMIT();
        for (int c = 0; c < NC2; c++) {
            if (c + 1 < NC2) { load2(c + 1, (c + 1) & 1); CP_COMMIT(); CP_WAIT1(); }
            else             { CP_WAIT0(); }
            __syncthreads();
            const float* W2s = WB + (c & 1) * 8192;
#pragma unroll
            for (int kk = 0; kk < KC2; kk++) {
                int kg = c * KC2 + kk;
                unsigned long long a2[8], b2[4];
#pragma unroll
                for (int i = 0; i < 8; i++) {
                    float av = Hs[(r0 + i) * MOE + kg];  // warp-broadcast LDS
                    a2[i] = pk2(av, av);
                }
#pragma unroll
                for (int j = 0; j < 4; j++)
                    b2[j] = *(const unsigned long long*)(W2s + kk * 256 + 2 * tx + 64 * j);
#pragma unroll
                for (int i = 0; i < 8; i++)
#pragma unroll
                    for (int j = 0; j < 4; j++) fma2(acc2[i][j], a2[i], b2[j]);
            }
            __syncthreads();
        }

        // write scaled rows to slot-indexed combine buffer (coalesced 64-bit)
#pragma unroll
        for (int i = 0; i < 8; i++) {
            int row = r0 + i;
            if (row < nr) {
                float wt = wt_s[row];
                float* dst = g_yb + (size_t)slot_s[row] * DIMV + nh * 256 + 2 * tx;
#pragma unroll
                for (int j = 0; j < 4; j++) {
                    float lo, hi; upk2(acc2[i][j], lo, hi);
                    *(float2*)(dst + 64 * j) = make_float2(lo * wt, hi * wt);
                }
            }
        }
    }
}

__global__ void k_combine(float* __restrict__ out) {
    int idx = blockIdx.x * 256 + threadIdx.x;       // T_TOK*DIMV = 1,048,576
    int t = idx >> 9, d = idx & 511;
    const float* p = g_yb + (size_t)t * TOPK * DIMV + d;
    float s = 0.f;
#pragma unroll
    for (int k = 0; k < TOPK; k++) s += p[(size_t)k * DIMV];
    out[idx] = s;
}

// ---------------------------------------------------------------------------
extern "C" void kernel_launch(void* const* d_in, const int* in_sizes, int n_in,
                              void* d_out, int out_size) {
    const float* x  = (const float*)d_in[0];
    const float* gw = (const float*)d_in[1];
    const float* gb = (const float*)d_in[2];
    const float* w1 = (const float*)d_in[3];
    const float* w3 = (const float*)d_in[4];
    const float* w2 = (const float*)d_in[5];
    float* out = (float*)d_out;

    (void)in_sizes; (void)n_in; (void)out_size;

    const int smem_bytes = (TM * DIMV + 16384) * sizeof(float);   // 196608
    cudaFuncSetAttribute(k_expert, cudaFuncAttributeMaxDynamicSharedMemorySize,
                         smem_bytes);

    k_init<<<1, 64>>>();
    k_gate<<<T_TOK / 8, 256>>>(x, gw, gb);
    k_expert<<<NEXP * TILES_PER_E, 256, smem_bytes>>>(x, w1, w3, w2);
    k_combine<<<(T_TOK * DIMV) / 256, 256>>>(out);
}

// round 7
// speedup vs baseline: 1.3274x; 1.3274x over previous
#include <cuda_runtime.h>
#include <cuda_bf16.h>
#include <cstdint>
#include <cstddef>

// Problem constants
#define T_TOK 2048
#define DIMV  512
#define MOE   256
#define NEXP  64
#define NGRP  8
#define TOPG  4
#define TOPK  8
#define CAPE  1024
#define RSCALE 2.5f

#define TM    64                 // token rows per expert tile
#define TILES (CAPE / TM)        // 16

// ---------------- device scratch (static; no allocations allowed) -----------
__device__ int   g_cnt[NEXP];
__device__ int   g_tok[NEXP * CAPE];
__device__ int   g_slot[NEXP * CAPE];
__device__ float g_wt[NEXP * CAPE];
__device__ float g_yb[(size_t)T_TOK * TOPK * DIMV];           // 33.5 MB

__device__ __nv_bfloat16 g_xh[(size_t)T_TOK * DIMV];           // 2 MB each
__device__ __nv_bfloat16 g_xl[(size_t)T_TOK * DIMV];
// W13T[e][n'(512)][k(512)], n' = hidden_col*2 + {0:w1, 1:w3} (interleaved)
__device__ __nv_bfloat16 g_w13h[(size_t)NEXP * 512 * 512];     // 32 MB each
__device__ __nv_bfloat16 g_w13l[(size_t)NEXP * 512 * 512];
// W2T[e][d(512)][m(256)]
__device__ __nv_bfloat16 g_w2h[(size_t)NEXP * 512 * 256];      // 16 MB each
__device__ __nv_bfloat16 g_w2l[(size_t)NEXP * 512 * 256];

// ---------------- helpers ----------------------------------------------------
__device__ __forceinline__ unsigned su32(const void* p) {
    return (unsigned)__cvta_generic_to_shared(p);
}
#define CP16(daddr, src) \
    asm volatile("cp.async.cg.shared.global [%0], [%1], 16;\n" :: "r"(daddr), "l"(src))
#define CP_COMMIT() asm volatile("cp.async.commit_group;\n")
#define CP_WAIT1()  asm volatile("cp.async.wait_group 1;\n" ::: "memory")
#define CP_WAIT0()  asm volatile("cp.async.wait_group 0;\n" ::: "memory")

__device__ __forceinline__ void ldsm4(uint32_t* r, uint32_t a) {
    asm volatile("ldmatrix.sync.aligned.m8n8.x4.shared.b16 {%0,%1,%2,%3}, [%4];"
        : "=r"(r[0]), "=r"(r[1]), "=r"(r[2]), "=r"(r[3]) : "r"(a));
}
__device__ __forceinline__ void ldsm2(uint32_t* r, uint32_t a) {
    asm volatile("ldmatrix.sync.aligned.m8n8.x2.shared.b16 {%0,%1}, [%2];"
        : "=r"(r[0]), "=r"(r[1]) : "r"(a));
}
__device__ __forceinline__ void mmabf(float* c, const uint32_t* a, const uint32_t* b) {
    asm volatile("mma.sync.aligned.m16n8k16.row.col.f32.bf16.bf16.f32 "
        "{%0,%1,%2,%3}, {%4,%5,%6,%7}, {%8,%9}, {%0,%1,%2,%3};"
        : "+f"(c[0]), "+f"(c[1]), "+f"(c[2]), "+f"(c[3])
        : "r"(a[0]), "r"(a[1]), "r"(a[2]), "r"(a[3]), "r"(b[0]), "r"(b[1]));
}

// conflict-free XOR swizzles (granule = 16 B)
__device__ __forceinline__ uint32_t xoff(int row, int kq) {   // 1024 B rows (X)
    return (uint32_t)(row * 1024 + (((kq & ~7) | ((kq ^ row) & 7)) << 4));
}
__device__ __forceinline__ uint32_t hoff(int row, int kq) {   // 512 B rows (H)
    return (uint32_t)(row * 512 + (((kq & ~7) | ((kq ^ row) & 7)) << 4));
}
__device__ __forceinline__ uint32_t boff(int n, int kh) {     // 32 B rows (B)
    return (uint32_t)(n * 32 + ((kh ^ ((n >> 2) & 1)) << 4));
}

// ---------------------------------------------------------------------------
__global__ void k_init() {
    if (threadIdx.x < NEXP) g_cnt[threadIdx.x] = 0;
}

__global__ void ksplit_x(const float* __restrict__ x) {
    int i = blockIdx.x * 256 + threadIdx.x;
    float v = x[i];
    __nv_bfloat16 h = __float2bfloat16(v);
    __nv_bfloat16 l = __float2bfloat16(v - __bfloat162float(h));
    g_xh[i] = h;
    g_xl[i] = l;
}

// w1/w3 [e][512 k][256 col] -> W13T [e][n'=col*2+m][k] hi/lo (k contiguous)
__global__ void ksplit_w13(const float* __restrict__ w1, const float* __restrict__ w3) {
    __shared__ float sm[32][33];
    int b = blockIdx.x;                 // 64*2*16*8 = 16384
    int e = b >> 8;
    int rem = b & 255;
    int m = rem >> 7;
    int rem2 = rem & 127;
    int kt = rem2 >> 3;                 // 0..15
    int ntl = rem2 & 7;                 // 0..7
    int tid = threadIdx.x;
    const float* src = m ? w3 : w1;
#pragma unroll
    for (int i = 0; i < 4; i++) {
        int kl = (tid >> 5) + i * 8;
        int nc = ntl * 32 + (tid & 31);
        sm[kl][tid & 31] = src[((size_t)e * 512 + kt * 32 + kl) * 256 + nc];
    }
    __syncthreads();
#pragma unroll
    for (int i = 0; i < 4; i++) {
        int nl = (tid >> 5) + i * 8;
        int kl = tid & 31;
        float v = sm[kl][nl];
        __nv_bfloat16 h = __float2bfloat16(v);
        __nv_bfloat16 l = __float2bfloat16(v - __bfloat162float(h));
        int np = (ntl * 32 + nl) * 2 + m;     // interleaved n'
        size_t o = ((size_t)e * 512 + np) * 512 + kt * 32 + kl;
        g_w13h[o] = h;
        g_w13l[o] = l;
    }
}

// w2 [e][256 m][512 d] -> W2T [e][d][m] hi/lo
__global__ void ksplit_w2(const float* __restrict__ w2) {
    __shared__ float sm[32][33];
    int b = blockIdx.x;                 // 64*8*16 = 8192
    int e = b >> 7;
    int rem = b & 127;
    int kt = rem >> 4;                  // 0..7  (m tiles)
    int ntl = rem & 15;                 // 0..15 (d tiles)
    int tid = threadIdx.x;
#pragma unroll
    for (int i = 0; i < 4; i++) {
        int ml = (tid >> 5) + i * 8;
        int d = ntl * 32 + (tid & 31);
        sm[ml][tid & 31] = w2[((size_t)e * 256 + kt * 32 + ml) * 512 + d];
    }
    __syncthreads();
#pragma unroll
    for (int i = 0; i < 4; i++) {
        int dl = (tid >> 5) + i * 8;
        int ml = tid & 31;
        float v = sm[ml][dl];
        __nv_bfloat16 h = __float2bfloat16(v);
        __nv_bfloat16 l = __float2bfloat16(v - __bfloat162float(h));
        size_t o = ((size_t)e * 512 + ntl * 32 + dl) * 256 + kt * 32 + ml;
        g_w2h[o] = h;
        g_w2l[o] = l;
    }
}

// ---------------- gating (unchanged, proven) --------------------------------
__global__ void __launch_bounds__(256) k_gate(const float* __restrict__ x,
                                              const float* __restrict__ gw,
                                              const float* __restrict__ gb) {
    __shared__ float wbuf[8 * DIMV];
    __shared__ float sc[8][NEXP];
    __shared__ float sb[8][NEXP];
    __shared__ float gbs[NEXP];

    int tid = threadIdx.x;
    int w = tid >> 5, lane = tid & 31;
    int t = blockIdx.x * 8 + w;

    if (tid < NEXP) gbs[tid] = gb[tid];

    float xr[16];
#pragma unroll
    for (int i = 0; i < 16; i++) xr[i] = x[(size_t)t * DIMV + lane + 32 * i];

    for (int ec = 0; ec < NEXP / 8; ec++) {
        __syncthreads();
#pragma unroll
        for (int q = 0; q < 16; q++) {
            int idx = q * 256 + tid;
            wbuf[idx] = gw[(size_t)(ec * 8) * DIMV + idx];
        }
        __syncthreads();
#pragma unroll
        for (int j = 0; j < 8; j++) {
            float s = 0.f;
#pragma unroll
            for (int i = 0; i < 16; i++) s += xr[i] * wbuf[j * DIMV + lane + 32 * i];
#pragma unroll
            for (int off = 16; off; off >>= 1) s += __shfl_xor_sync(0xffffffffu, s, off);
            if (lane == 0) sc[w][ec * 8 + j] = 1.f / (1.f + __expf(-s));
        }
    }
    __syncthreads();

    if (lane == 0) {
        float* scw = sc[w];
        float* sbw = sb[w];
        float gs[NGRP];
        for (int g = 0; g < NGRP; g++) {
            float m1 = -1e30f, m2 = -1e30f;
            for (int j = 0; j < 8; j++) {
                float v = scw[g * 8 + j] + gbs[g * 8 + j];
                if (v > m1) { m2 = m1; m1 = v; }
                else if (v > m2) { m2 = v; }
            }
            gs[g] = m1 + m2;
        }
        unsigned allowed = 0;
        for (int p = 0; p < TOPG; p++) {
            float best = -1e30f; int bi = 0;
            for (int g = 0; g < NGRP; g++)
                if (!((allowed >> g) & 1) && gs[g] > best) { best = gs[g]; bi = g; }
            allowed |= 1u << bi;
        }
        for (int e = 0; e < NEXP; e++)
            sbw[e] = ((allowed >> (e >> 3)) & 1) ? scw[e] + gbs[e] : -1e30f;
        int idxs[TOPK]; float wsum = 0.f;
        for (int p = 0; p < TOPK; p++) {
            float best = -1e30f; int bi = 0;
            for (int e = 0; e < NEXP; e++)
                if (sbw[e] > best) { best = sbw[e]; bi = e; }
            idxs[p] = bi; sbw[bi] = -1e30f;
            wsum += scw[bi];
        }
        float inv = RSCALE / wsum;
        for (int p = 0; p < TOPK; p++) {
            int e = idxs[p];
            int pos = atomicAdd(&g_cnt[e], 1);
            if (pos < CAPE) {
                g_tok[e * CAPE + pos]  = t;
                g_slot[e * CAPE + pos] = t * TOPK + p;
                g_wt[e * CAPE + pos]   = scw[e] * inv;
            }
        }
    }
}

// ---------------- expert FFN: bf16 hi/lo 3-pass HMMA ------------------------
// smem layout (SB, 1024-aligned):
//   [0,      65536): Xh [64][1024B rows, swizzled]; reused as Hh (32 KB) + Hl (at +32768)
//   [65536, 131072): Xl
//   [131072,196608): B double buffer: buf*32768 + {Bh:0, Bl:16384}
__global__ void __launch_bounds__(256, 1)
k_expert_mma() {
    extern __shared__ char smraw[];
    char* SB = (char*)(((uintptr_t)smraw + 1023) & ~(uintptr_t)1023);
    __shared__ int   tok_s[TM];
    __shared__ int   slot_s[TM];
    __shared__ float wt_s[TM];

    int e    = blockIdx.x >> 4;
    int tile = blockIdx.x & (TILES - 1);
    int tid  = threadIdx.x;
    int wid  = tid >> 5, lane = tid & 31;
    int wm = wid & 1, wn = wid >> 1;

    int n = min(g_cnt[e], CAPE);
    int r0g = tile * TM;
    if (r0g >= n) return;                        // uniform over block
    int nr = min(TM, n - r0g);

    if (tid < TM) {
        int ok = tid < nr;
        tok_s[tid]  = ok ? g_tok[e * CAPE + r0g + tid]  : 0;
        slot_s[tid] = ok ? g_slot[e * CAPE + r0g + tid] : 0;
        wt_s[tid]   = ok ? g_wt[e * CAPE + r0g + tid]   : 0.f;
    }
    __syncthreads();

    uint32_t sbase = su32(SB);

    // ---- X gather (hi+lo): 8192 granules ----
#pragma unroll
    for (int q = 0; q < 32; q++) {
        int idx = q * 256 + tid;
        int piece = idx >> 12;            // 0:hi 1:lo
        int g = idx & 4095;
        int row = g >> 6, kq = g & 63;
        const __nv_bfloat16* src = (piece ? g_xl : g_xh) +
                                   (size_t)tok_s[row] * DIMV + kq * 8;
        CP16(sbase + piece * 65536 + xoff(row, kq), src);
    }

    // ---- B chunk loaders ----
    auto loadB1 = [&](int kc, int buf) {
        uint32_t dst0 = sbase + 131072 + (uint32_t)buf * 32768;
#pragma unroll
        for (int q = 0; q < 8; q++) {
            int idx = q * 256 + tid;
            int piece = idx >> 10;
            int g = idx & 1023;
            int nn = g >> 1, kh = g & 1;
            const __nv_bfloat16* src = (piece ? g_w13l : g_w13h) +
                ((size_t)(e * 512 + nn)) * 512 + kc * 16 + kh * 8;
            CP16(dst0 + piece * 16384 + boff(nn, kh), src);
        }
    };
    auto loadB2 = [&](int kc, int buf) {
        uint32_t dst0 = sbase + 131072 + (uint32_t)buf * 32768;
#pragma unroll
        for (int q = 0; q < 8; q++) {
            int idx = q * 256 + tid;
            int piece = idx >> 10;
            int g = idx & 1023;
            int nn = g >> 1, kh = g & 1;
            const __nv_bfloat16* src = (piece ? g_w2l : g_w2h) +
                ((size_t)(e * 512 + nn)) * 256 + kc * 16 + kh * 8;
            CP16(dst0 + piece * 16384 + boff(nn, kh), src);
        }
    };

    loadB1(0, 0);
    CP_COMMIT();    // group: X + B1(0)

    // lane decompositions
    int lrow = lane & 7, lm = (lane >> 3) & 1, lkh = lane >> 4;
    int bn = lane & 7, bkh = (lane >> 3) & 1;

    // ================= GEMM1: [64,512] x W13T -> z (n' interleaved) =========
    float acc[2][16][4];
#pragma unroll
    for (int mt = 0; mt < 2; mt++)
#pragma unroll
        for (int j = 0; j < 16; j++)
#pragma unroll
            for (int v = 0; v < 4; v++) acc[mt][j][v] = 0.f;

#pragma unroll 1
    for (int kc = 0; kc < 32; kc++) {
        if (kc + 1 < 32) { loadB1(kc + 1, (kc + 1) & 1); CP_COMMIT(); CP_WAIT1(); }
        else             { CP_WAIT0(); }
        __syncthreads();

        uint32_t ah[2][4], al[2][4];
#pragma unroll
        for (int mt = 0; mt < 2; mt++) {
            int row = wm * 32 + mt * 16 + lrow + lm * 8;
            int kq = kc * 2 + lkh;
            uint32_t off = xoff(row, kq);
            ldsm4(ah[mt], sbase + off);
            ldsm4(al[mt], sbase + 65536 + off);
        }
        uint32_t bb = sbase + 131072 + (uint32_t)(kc & 1) * 32768;
#pragma unroll
        for (int j = 0; j < 16; j++) {
            int nn = wn * 128 + j * 8 + bn;
            uint32_t bo = boff(nn, bkh);
            uint32_t bh[2], bl[2];
            ldsm2(bh, bb + bo);
            ldsm2(bl, bb + 16384 + bo);
#pragma unroll
            for (int mt = 0; mt < 2; mt++) {
                mmabf(acc[mt][j], ah[mt], bh);
                mmabf(acc[mt][j], al[mt], bh);
                mmabf(acc[mt][j], ah[mt], bl);
            }
        }
        __syncthreads();
    }

    // ---- Epilogue 1: (z1,z3) pairs in-register -> h bf16 hi/lo in smem -----
    // Hh at SB, Hl at SB+32768 (reusing Xh region; X fully consumed)
#pragma unroll
    for (int mt = 0; mt < 2; mt++)
#pragma unroll
        for (int j = 0; j < 16; j++) {
            float* c = acc[mt][j];
            int r1 = wm * 32 + mt * 16 + (lane >> 2);
            int r2 = r1 + 8;
            int cc = wn * 64 + j * 4 + (lane & 3);
            float h1 = (c[0] * c[1]) / (1.f + __expf(-c[0]));
            float h2 = (c[2] * c[3]) / (1.f + __expf(-c[2]));
            __nv_bfloat16 h1h = __float2bfloat16(h1);
            __nv_bfloat16 h2h = __float2bfloat16(h2);
            __nv_bfloat16 h1l = __float2bfloat16(h1 - __bfloat162float(h1h));
            __nv_bfloat16 h2l = __float2bfloat16(h2 - __bfloat162float(h2h));
            int kq = cc >> 3, ci = (cc & 7) * 2;
            *(__nv_bfloat16*)(SB + hoff(r1, kq) + ci)         = h1h;
            *(__nv_bfloat16*)(SB + hoff(r2, kq) + ci)         = h2h;
            *(__nv_bfloat16*)(SB + 32768 + hoff(r1, kq) + ci) = h1l;
            *(__nv_bfloat16*)(SB + 32768 + hoff(r2, kq) + ci) = h2l;
        }
    __syncthreads();

    // ================= GEMM2: [64,256] x W2T -> Y [64,512] ==================
    float acc2[2][16][4];
#pragma unroll
    for (int mt = 0; mt < 2; mt++)
#pragma unroll
        for (int j = 0; j < 16; j++)
#pragma unroll
            for (int v = 0; v < 4; v++) acc2[mt][j][v] = 0.f;

    loadB2(0, 0);
    CP_COMMIT();
#pragma unroll 1
    for (int kc = 0; kc < 16; kc++) {
        if (kc + 1 < 16) { loadB2(kc + 1, (kc + 1) & 1); CP_COMMIT(); CP_WAIT1(); }
        else             { CP_WAIT0(); }
        __syncthreads();

        uint32_t ah[2][4], al[2][4];
#pragma unroll
        for (int mt = 0; mt < 2; mt++) {
            int row = wm * 32 + mt * 16 + lrow + lm * 8;
            int kq = kc * 2 + lkh;
            uint32_t off = hoff(row, kq);
            ldsm4(ah[mt], sbase + off);
            ldsm4(al[mt], sbase + 32768 + off);
        }
        uint32_t bb = sbase + 131072 + (uint32_t)(kc & 1) * 32768;
#pragma unroll
        for (int j = 0; j < 16; j++) {
            int nn = wn * 128 + j * 8 + bn;
            uint32_t bo = boff(nn, bkh);
            uint32_t bh[2], bl[2];
            ldsm2(bh, bb + bo);
            ldsm2(bl, bb + 16384 + bo);
#pragma unroll
            for (int mt = 0; mt < 2; mt++) {
                mmabf(acc2[mt][j], ah[mt], bh);
                mmabf(acc2[mt][j], al[mt], bh);
                mmabf(acc2[mt][j], ah[mt], bl);
            }
        }
        __syncthreads();
    }

    // ---- Epilogue 2: scale rows + scatter to combine buffer ----------------
#pragma unroll
    for (int mt = 0; mt < 2; mt++)
#pragma unroll
        for (int j = 0; j < 16; j++) {
            float* c = acc2[mt][j];
            int r1 = wm * 32 + mt * 16 + (lane >> 2);
            int r2 = r1 + 8;
            int d = wn * 128 + j * 8 + (lane & 3) * 2;
            if (r1 < nr) {
                float wt = wt_s[r1];
                *(float2*)(g_yb + (size_t)slot_s[r1] * DIMV + d) =
                    make_float2(c[0] * wt, c[1] * wt);
            }
            if (r2 < nr) {
                float wt = wt_s[r2];
                *(float2*)(g_yb + (size_t)slot_s[r2] * DIMV + d) =
                    make_float2(c[2] * wt, c[3] * wt);
            }
        }
}

__global__ void k_combine(float* __restrict__ out) {
    int idx = blockIdx.x * 256 + threadIdx.x;
    int t = idx >> 9, d = idx & 511;
    const float* p = g_yb + (size_t)t * TOPK * DIMV + d;
    float s = 0.f;
#pragma unroll
    for (int k = 0; k < TOPK; k++) s += p[(size_t)k * DIMV];
    out[idx] = s;
}

// ---------------------------------------------------------------------------
extern "C" void kernel_launch(void* const* d_in, const int* in_sizes, int n_in,
                              void* d_out, int out_size) {
    const float* x  = (const float*)d_in[0];
    const float* gw = (const float*)d_in[1];
    const float* gb = (const float*)d_in[2];
    const float* w1 = (const float*)d_in[3];
    const float* w3 = (const float*)d_in[4];
    const float* w2 = (const float*)d_in[5];
    float* out = (float*)d_out;

    (void)in_sizes; (void)n_in; (void)out_size;

    const int smem_bytes = 196608 + 1024;
    cudaFuncSetAttribute(k_expert_mma, cudaFuncAttributeMaxDynamicSharedMemorySize,
                         smem_bytes);

    k_init<<<1, 64>>>();
    ksplit_x<<<(T_TOK * DIMV) / 256, 256>>>(x);
    ksplit_w13<<<16384, 256>>>(w1, w3);
    ksplit_w2<<<8192, 256>>>(w2);
    k_gate<<<T_TOK / 8, 256>>>(x, gw, gb);
    k_expert_mma<<<NEXP * TILES, 256, smem_bytes>>>();
    k_combine<<<(T_TOK * DIMV) / 256, 256>>>(out);
}

// round 8
// speedup vs baseline: 1.4892x; 1.1218x over previous
#include <cuda_runtime.h>
#include <cuda_bf16.h>
#include <cstdint>
#include <cstddef>

// Problem constants
#define T_TOK 2048
#define DIMV  512
#define MOE   256
#define NEXP  64
#define NGRP  8
#define TOPG  4
#define TOPK  8
#define CAPE  1024
#define RSCALE 2.5f

#define TM    64                 // token rows per expert tile
#define TILES (CAPE / TM)        // 16
#define NC1   32                 // GEMM1 k-chunks (512/16)
#define NC2   16                 // GEMM2 k-chunks (256/16)

// smem map (SB 1024-aligned):
//   [0,      65536): Xh ; reused after GEMM1 as Hh (32 KB @0) + Hl (32 KB @32768)
//   [65536, 131072): Xl
//   [131072,229376): B stages: 3 x 32 KB, each {hi:16 KB, lo:16 KB}
#define SM_XL  65536u
#define SM_B   131072u
#define SM_BYTES (229376 + 1024)

// ---------------- device scratch (static; no allocations allowed) -----------
__device__ int   g_cnt[NEXP];
__device__ int   g_tok[NEXP * CAPE];
__device__ int   g_slot[NEXP * CAPE];
__device__ float g_wt[NEXP * CAPE];
__device__ float g_yb[(size_t)T_TOK * TOPK * DIMV];           // 33.5 MB

__device__ __nv_bfloat16 g_xh[(size_t)T_TOK * DIMV];
__device__ __nv_bfloat16 g_xl[(size_t)T_TOK * DIMV];
// W13T[e][n'(512)][k(512)], n' = hidden_col*2 + {0:w1, 1:w3}
__device__ __nv_bfloat16 g_w13h[(size_t)NEXP * 512 * 512];
__device__ __nv_bfloat16 g_w13l[(size_t)NEXP * 512 * 512];
// W2T[e][d(512)][m(256)]
__device__ __nv_bfloat16 g_w2h[(size_t)NEXP * 512 * 256];
__device__ __nv_bfloat16 g_w2l[(size_t)NEXP * 512 * 256];

// ---------------- helpers ----------------------------------------------------
__device__ __forceinline__ unsigned su32(const void* p) {
    return (unsigned)__cvta_generic_to_shared(p);
}
#define CP16(daddr, src) \
    asm volatile("cp.async.cg.shared.global [%0], [%1], 16;\n" :: "r"(daddr), "l"(src))
#define CP_COMMIT() asm volatile("cp.async.commit_group;\n")
#define CP_WAIT1()  asm volatile("cp.async.wait_group 1;\n" ::: "memory")
#define CP_WAIT0()  asm volatile("cp.async.wait_group 0;\n" ::: "memory")

__device__ __forceinline__ void ldsm4(uint32_t* r, uint32_t a) {
    asm volatile("ldmatrix.sync.aligned.m8n8.x4.shared.b16 {%0,%1,%2,%3}, [%4];"
        : "=r"(r[0]), "=r"(r[1]), "=r"(r[2]), "=r"(r[3]) : "r"(a));
}
__device__ __forceinline__ void mmabf(float* c, const uint32_t* a, const uint32_t* b) {
    asm volatile("mma.sync.aligned.m16n8k16.row.col.f32.bf16.bf16.f32 "
        "{%0,%1,%2,%3}, {%4,%5,%6,%7}, {%8,%9}, {%0,%1,%2,%3};"
        : "+f"(c[0]), "+f"(c[1]), "+f"(c[2]), "+f"(c[3])
        : "r"(a[0]), "r"(a[1]), "r"(a[2]), "r"(a[3]), "r"(b[0]), "r"(b[1]));
}

// conflict-free XOR swizzles (granule = 16 B)
__device__ __forceinline__ uint32_t xoff(int row, int kq) {   // 1024 B rows (X)
    return (uint32_t)(row * 1024 + (((kq & ~7) | ((kq ^ row) & 7)) << 4));
}
__device__ __forceinline__ uint32_t hoff(int row, int kq) {   // 512 B rows (H)
    return (uint32_t)(row * 512 + (((kq & ~7) | ((kq ^ row) & 7)) << 4));
}
__device__ __forceinline__ uint32_t boff(int n, int kh) {     // 32 B rows (B)
    return (uint32_t)(n * 32 + ((kh ^ ((n >> 2) & 1)) << 4));
}

// ---------------------------------------------------------------------------
__global__ void k_init() {
    if (threadIdx.x < NEXP) g_cnt[threadIdx.x] = 0;
}

__global__ void ksplit_x(const float* __restrict__ x) {
    int i = blockIdx.x * 256 + threadIdx.x;
    float v = x[i];
    __nv_bfloat16 h = __float2bfloat16(v);
    __nv_bfloat16 l = __float2bfloat16(v - __bfloat162float(h));
    g_xh[i] = h;
    g_xl[i] = l;
}

// w1/w3 [e][512 k][256 col] -> W13T [e][n'=col*2+m][k] hi/lo, packed 32-bit stores
__global__ void ksplit_w13(const float* __restrict__ w1, const float* __restrict__ w3) {
    __shared__ float sm[32][33];
    int b = blockIdx.x;                 // 64*2*16*8 = 16384
    int e = b >> 8;
    int rem = b & 255;
    int m = rem >> 7;
    int rem2 = rem & 127;
    int kt = rem2 >> 3;                 // 0..15
    int ntl = rem2 & 7;                 // 0..7
    int tid = threadIdx.x;
    const float* src = m ? w3 : w1;
#pragma unroll
    for (int i = 0; i < 4; i++) {
        int kl = (tid >> 5) + i * 8;
        int nc = ntl * 32 + (tid & 31);
        sm[kl][tid & 31] = src[((size_t)e * 512 + kt * 32 + kl) * 256 + nc];
    }
    __syncthreads();
#pragma unroll
    for (int i = 0; i < 2; i++) {
        int it = i * 256 + tid;         // 512 items = 32 n x 16 k-pairs
        int nl = it >> 4;
        int kp = it & 15;
        float v0 = sm[2 * kp][nl], v1 = sm[2 * kp + 1][nl];
        __nv_bfloat16 h0 = __float2bfloat16(v0), h1 = __float2bfloat16(v1);
        __nv_bfloat16 l0 = __float2bfloat16(v0 - __bfloat162float(h0));
        __nv_bfloat16 l1 = __float2bfloat16(v1 - __bfloat162float(h1));
        uint32_t ph = (uint32_t)__bfloat16_as_ushort(h0) |
                      ((uint32_t)__bfloat16_as_ushort(h1) << 16);
        uint32_t pl = (uint32_t)__bfloat16_as_ushort(l0) |
                      ((uint32_t)__bfloat16_as_ushort(l1) << 16);
        int np = (ntl * 32 + nl) * 2 + m;
        size_t o = (((size_t)e * 512 + np) * 512 + kt * 32 + 2 * kp) >> 1;
        ((uint32_t*)g_w13h)[o] = ph;
        ((uint32_t*)g_w13l)[o] = pl;
    }
}

// w2 [e][256 m][512 d] -> W2T [e][d][m] hi/lo, packed 32-bit stores
__global__ void ksplit_w2(const float* __restrict__ w2) {
    __shared__ float sm[32][33];
    int b = blockIdx.x;                 // 64*8*16 = 8192
    int e = b >> 7;
    int rem = b & 127;
    int kt = rem >> 4;                  // 0..7  (m tiles)
    int ntl = rem & 15;                 // 0..15 (d tiles)
    int tid = threadIdx.x;
#pragma unroll
    for (int i = 0; i < 4; i++) {
        int ml = (tid >> 5) + i * 8;
        int d = ntl * 32 + (tid & 31);
        sm[ml][tid & 31] = w2[((size_t)e * 256 + kt * 32 + ml) * 512 + d];
    }
    __syncthreads();
#pragma unroll
    for (int i = 0; i < 2; i++) {
        int it = i * 256 + tid;
        int dl = it >> 4;
        int kp = it & 15;
        float v0 = sm[2 * kp][dl], v1 = sm[2 * kp + 1][dl];
        __nv_bfloat16 h0 = __float2bfloat16(v0), h1 = __float2bfloat16(v1);
        __nv_bfloat16 l0 = __float2bfloat16(v0 - __bfloat162float(h0));
        __nv_bfloat16 l1 = __float2bfloat16(v1 - __bfloat162float(h1));
        uint32_t ph = (uint32_t)__bfloat16_as_ushort(h0) |
                      ((uint32_t)__bfloat16_as_ushort(h1) << 16);
        uint32_t pl = (uint32_t)__bfloat16_as_ushort(l0) |
                      ((uint32_t)__bfloat16_as_ushort(l1) << 16);
        size_t o = (((size_t)e * 512 + ntl * 32 + dl) * 256 + kt * 32 + 2 * kp) >> 1;
        ((uint32_t*)g_w2h)[o] = ph;
        ((uint32_t*)g_w2l)[o] = pl;
    }
}

// ---------------- gating (unchanged, proven) --------------------------------
__global__ void __launch_bounds__(256) k_gate(const float* __restrict__ x,
                                              const float* __restrict__ gw,
                                              const float* __restrict__ gb) {
    __shared__ float wbuf[8 * DIMV];
    __shared__ float sc[8][NEXP];
    __shared__ float sb[8][NEXP];
    __shared__ float gbs[NEXP];

    int tid = threadIdx.x;
    int w = tid >> 5, lane = tid & 31;
    int t = blockIdx.x * 8 + w;

    if (tid < NEXP) gbs[tid] = gb[tid];

    float xr[16];
#pragma unroll
    for (int i = 0; i < 16; i++) xr[i] = x[(size_t)t * DIMV + lane + 32 * i];

    for (int ec = 0; ec < NEXP / 8; ec++) {
        __syncthreads();
#pragma unroll
        for (int q = 0; q < 16; q++) {
            int idx = q * 256 + tid;
            wbuf[idx] = gw[(size_t)(ec * 8) * DIMV + idx];
        }
        __syncthreads();
#pragma unroll
        for (int j = 0; j < 8; j++) {
            float s = 0.f;
#pragma unroll
            for (int i = 0; i < 16; i++) s += xr[i] * wbuf[j * DIMV + lane + 32 * i];
#pragma unroll
            for (int off = 16; off; off >>= 1) s += __shfl_xor_sync(0xffffffffu, s, off);
            if (lane == 0) sc[w][ec * 8 + j] = 1.f / (1.f + __expf(-s));
        }
    }
    __syncthreads();

    if (lane == 0) {
        float* scw = sc[w];
        float* sbw = sb[w];
        float gs[NGRP];
        for (int g = 0; g < NGRP; g++) {
            float m1 = -1e30f, m2 = -1e30f;
            for (int j = 0; j < 8; j++) {
                float v = scw[g * 8 + j] + gbs[g * 8 + j];
                if (v > m1) { m2 = m1; m1 = v; }
                else if (v > m2) { m2 = v; }
            }
            gs[g] = m1 + m2;
        }
        unsigned allowed = 0;
        for (int p = 0; p < TOPG; p++) {
            float best = -1e30f; int bi = 0;
            for (int g = 0; g < NGRP; g++)
                if (!((allowed >> g) & 1) && gs[g] > best) { best = gs[g]; bi = g; }
            allowed |= 1u << bi;
        }
        for (int e = 0; e < NEXP; e++)
            sbw[e] = ((allowed >> (e >> 3)) & 1) ? scw[e] + gbs[e] : -1e30f;
        int idxs[TOPK]; float wsum = 0.f;
        for (int p = 0; p < TOPK; p++) {
            float best = -1e30f; int bi = 0;
            for (int e = 0; e < NEXP; e++)
                if (sbw[e] > best) { best = sbw[e]; bi = e; }
            idxs[p] = bi; sbw[bi] = -1e30f;
            wsum += scw[bi];
        }
        float inv = RSCALE / wsum;
        for (int p = 0; p < TOPK; p++) {
            int e = idxs[p];
            int pos = atomicAdd(&g_cnt[e], 1);
            if (pos < CAPE) {
                g_tok[e * CAPE + pos]  = t;
                g_slot[e * CAPE + pos] = t * TOPK + p;
                g_wt[e * CAPE + pos]   = scw[e] * inv;
            }
        }
    }
}

// ---------------- expert FFN: bf16 hi/lo 3-pass HMMA, 512 threads -----------
__global__ void __launch_bounds__(512, 1)
k_expert_mma() {
    extern __shared__ char smraw[];
    char* SB = (char*)(((uintptr_t)smraw + 1023) & ~(uintptr_t)1023);
    __shared__ int   tok_s[TM];
    __shared__ int   slot_s[TM];
    __shared__ float wt_s[TM];

    int e    = blockIdx.x >> 4;
    int tile = blockIdx.x & (TILES - 1);
    int tid  = threadIdx.x;
    int wid  = tid >> 5, lane = tid & 31;
    int wm = wid & 3, wn = wid >> 2;          // 4 x 4 warp grid

    int n = min(g_cnt[e], CAPE);
    int r0g = tile * TM;
    if (r0g >= n) return;                     // uniform over block
    int nr = min(TM, n - r0g);

    if (tid < TM) {
        int ok = tid < nr;
        tok_s[tid]  = ok ? g_tok[e * CAPE + r0g + tid]  : 0;
        slot_s[tid] = ok ? g_slot[e * CAPE + r0g + tid] : 0;
        wt_s[tid]   = ok ? g_wt[e * CAPE + r0g + tid]   : 0.f;
    }
    __syncthreads();

    uint32_t sbase = su32(SB);

    // ---- B chunk loaders (32 KB = 2048 granules; 4 iters x 512 threads) ----
    auto loadB1 = [&](int kc, int st) {
        uint32_t dst0 = sbase + SM_B + (uint32_t)st * 32768u;
#pragma unroll
        for (int q = 0; q < 4; q++) {
            int idx = q * 512 + tid;
            int piece = idx >> 10;
            int g = idx & 1023;
            int nn = g >> 1, kh = g & 1;
            const __nv_bfloat16* src = (piece ? g_w13l : g_w13h) +
                ((size_t)(e * 512 + nn)) * 512 + kc * 16 + kh * 8;
            CP16(dst0 + piece * 16384 + boff(nn, kh), src);
        }
    };
    auto loadB2 = [&](int kc, int st) {
        uint32_t dst0 = sbase + SM_B + (uint32_t)st * 32768u;
#pragma unroll
        for (int q = 0; q < 4; q++) {
            int idx = q * 512 + tid;
            int piece = idx >> 10;
            int g = idx & 1023;
            int nn = g >> 1, kh = g & 1;
            const __nv_bfloat16* src = (piece ? g_w2l : g_w2h) +
                ((size_t)(e * 512 + nn)) * 256 + kc * 16 + kh * 8;
            CP16(dst0 + piece * 16384 + boff(nn, kh), src);
        }
    };

    // ---- Prologue: X gather (hi+lo, 8192 granules) + B1(0) in group0; B1(1) group1
#pragma unroll
    for (int q = 0; q < 16; q++) {
        int idx = q * 512 + tid;
        int piece = idx >> 12;
        int g = idx & 4095;
        int row = g >> 6, kq = g & 63;
        const __nv_bfloat16* src = (piece ? g_xl : g_xh) +
                                   (size_t)tok_s[row] * DIMV + kq * 8;
        CP16(sbase + (uint32_t)piece * SM_XL + xoff(row, kq), src);
    }
    loadB1(0, 0);
    CP_COMMIT();
    loadB1(1, 1);
    CP_COMMIT();

    // lane decompositions
    int lrow = lane & 7, lm = (lane >> 3) & 1, lkh = lane >> 4;   // A ldsm4
    int bN = ((lane >> 4) & 1) * 8 + (lane & 7);                   // B ldsm4 n-offset
    int bKH = (lane >> 3) & 1;                                     // B k-half

    // ================= GEMM1: [64,512] x W13T -> z (n' interleaved) =========
    float acc[16][4];
#pragma unroll
    for (int j = 0; j < 16; j++)
#pragma unroll
        for (int v = 0; v < 4; v++) acc[j][v] = 0.f;

#pragma unroll 1
    for (int kc = 0; kc < NC1; kc++) {
        if (kc < NC1 - 1) CP_WAIT1(); else CP_WAIT0();
        __syncthreads();

        uint32_t ah[4], al[4];
        {
            int row = wm * 16 + lrow + lm * 8;
            int kq = kc * 2 + lkh;
            uint32_t off = xoff(row, kq);
            ldsm4(ah, sbase + off);
            ldsm4(al, sbase + SM_XL + off);
        }
        uint32_t bb = sbase + SM_B + (uint32_t)(kc % 3) * 32768u;
#pragma unroll
        for (int j2 = 0; j2 < 8; j2++) {
            int nn = wn * 128 + j2 * 16 + bN;
            uint32_t bo = boff(nn, bKH);
            uint32_t bh[4], bl[4];
            ldsm4(bh, bb + bo);
            ldsm4(bl, bb + 16384 + bo);
            mmabf(acc[2 * j2],     ah, bh);
            mmabf(acc[2 * j2],     al, bh);
            mmabf(acc[2 * j2],     ah, bl);
            mmabf(acc[2 * j2 + 1], ah, bh + 2);
            mmabf(acc[2 * j2 + 1], al, bh + 2);
            mmabf(acc[2 * j2 + 1], ah, bl + 2);
        }
        if (kc + 2 < NC1) { loadB1(kc + 2, (kc + 2) % 3); CP_COMMIT(); }
    }
    __syncthreads();                          // all X reads done before H overwrite

    // ---- Epilogue 1: (z1,z3) in-register -> h bf16 hi/lo in smem -----------
    // Hh @ SB, Hl @ SB+32768 (reusing Xh region)
    {
        int r1 = wm * 16 + (lane >> 2);
        int r2 = r1 + 8;
#pragma unroll
        for (int j = 0; j < 16; j++) {
            float* c = acc[j];
            int cc = wn * 64 + j * 4 + (lane & 3);     // hidden col
            float h1 = (c[0] * c[1]) / (1.f + __expf(-c[0]));
            float h2 = (c[2] * c[3]) / (1.f + __expf(-c[2]));
            __nv_bfloat16 h1h = __float2bfloat16(h1);
            __nv_bfloat16 h2h = __float2bfloat16(h2);
            __nv_bfloat16 h1l = __float2bfloat16(h1 - __bfloat162float(h1h));
            __nv_bfloat16 h2l = __float2bfloat16(h2 - __bfloat162float(h2h));
            int kq = cc >> 3, ci = (cc & 7) * 2;
            *(__nv_bfloat16*)(SB + hoff(r1, kq) + ci)         = h1h;
            *(__nv_bfloat16*)(SB + hoff(r2, kq) + ci)         = h2h;
            *(__nv_bfloat16*)(SB + 32768 + hoff(r1, kq) + ci) = h1l;
            *(__nv_bfloat16*)(SB + 32768 + hoff(r2, kq) + ci) = h2l;
        }
    }
    loadB2(0, 0);
    CP_COMMIT();
    loadB2(1, 1);
    CP_COMMIT();
    __syncthreads();                          // H visible to all warps

    // ================= GEMM2: [64,256] x W2T -> Y [64,512] ==================
    float acc2[16][4];
#pragma unroll
    for (int j = 0; j < 16; j++)
#pragma unroll
        for (int v = 0; v < 4; v++) acc2[j][v] = 0.f;

#pragma unroll 1
    for (int kc = 0; kc < NC2; kc++) {
        if (kc < NC2 - 1) CP_WAIT1(); else CP_WAIT0();
        __syncthreads();

        uint32_t ah[4], al[4];
        {
            int row = wm * 16 + lrow + lm * 8;
            int kq = kc * 2 + lkh;
            uint32_t off = hoff(row, kq);
            ldsm4(ah, sbase + off);
            ldsm4(al, sbase + 32768 + off);
        }
        uint32_t bb = sbase + SM_B + (uint32_t)(kc % 3) * 32768u;
#pragma unroll
        for (int j2 = 0; j2 < 8; j2++) {
            int nn = wn * 128 + j2 * 16 + bN;
            uint32_t bo = boff(nn, bKH);
            uint32_t bh[4], bl[4];
            ldsm4(bh, bb + bo);
            ldsm4(bl, bb + 16384 + bo);
            mmabf(acc2[2 * j2],     ah, bh);
            mmabf(acc2[2 * j2],     al, bh);
            mmabf(acc2[2 * j2],     ah, bl);
            mmabf(acc2[2 * j2 + 1], ah, bh + 2);
            mmabf(acc2[2 * j2 + 1], al, bh + 2);
            mmabf(acc2[2 * j2 + 1], ah, bl + 2);
        }
        if (kc + 2 < NC2) { loadB2(kc + 2, (kc + 2) % 3); CP_COMMIT(); }
    }

    // ---- Epilogue 2: scale rows + scatter to combine buffer ----------------
    {
        int r1 = wm * 16 + (lane >> 2);
        int r2 = r1 + 8;
        float w1s = (r1 < nr) ? wt_s[r1] : 0.f;
        float w2s = (r2 < nr) ? wt_s[r2] : 0.f;
        size_t s1 = (r1 < nr) ? (size_t)slot_s[r1] : 0;
        size_t s2 = (r2 < nr) ? (size_t)slot_s[r2] : 0;
#pragma unroll
        for (int j = 0; j < 16; j++) {
            float* c = acc2[j];
            int d = wn * 128 + j * 8 + (lane & 3) * 2;
            if (r1 < nr)
                *(float2*)(g_yb + s1 * DIMV + d) = make_float2(c[0] * w1s, c[1] * w1s);
            if (r2 < nr)
                *(float2*)(g_yb + s2 * DIMV + d) = make_float2(c[2] * w2s, c[3] * w2s);
        }
    }
}

__global__ void k_combine(float* __restrict__ out) {
    int idx = blockIdx.x * 256 + threadIdx.x;        // T*DIMV/4 = 262144
    int t = idx >> 7, d4 = idx & 127;
    const float4* p = (const float4*)(g_yb + (size_t)t * TOPK * DIMV) + d4;
    float4 s = make_float4(0.f, 0.f, 0.f, 0.f);
#pragma unroll
    for (int k = 0; k < TOPK; k++) {
        float4 v = p[k * (DIMV / 4)];
        s.x += v.x; s.y += v.y; s.z += v.z; s.w += v.w;
    }
    ((float4*)out)[idx] = s;
}

// ---------------------------------------------------------------------------
extern "C" void kernel_launch(void* const* d_in, const int* in_sizes, int n_in,
                              void* d_out, int out_size) {
    const float* x  = (const float*)d_in[0];
    const float* gw = (const float*)d_in[1];
    const float* gb = (const float*)d_in[2];
    const float* w1 = (const float*)d_in[3];
    const float* w3 = (const float*)d_in[4];
    const float* w2 = (const float*)d_in[5];
    float* out = (float*)d_out;

    (void)in_sizes; (void)n_in; (void)out_size;

    cudaFuncSetAttribute(k_expert_mma, cudaFuncAttributeMaxDynamicSharedMemorySize,
                         SM_BYTES);

    k_init<<<1, 64>>>();
    ksplit_x<<<(T_TOK * DIMV) / 256, 256>>>(x);
    ksplit_w13<<<16384, 256>>>(w1, w3);
    ksplit_w2<<<8192, 256>>>(w2);
    k_gate<<<T_TOK / 8, 256>>>(x, gw, gb);
    k_expert_mma<<<NEXP * TILES, 512, SM_BYTES>>>();
    k_combine<<<(T_TOK * DIMV) / 4 / 256, 256>>>(out);
}

// round 11
// speedup vs baseline: 1.5580x; 1.0462x over previous
#include <cuda_runtime.h>
#include <cuda_bf16.h>
#include <cstdint>
#include <cstddef>

// Problem constants
#define T_TOK 2048
#define DIMV  512
#define MOE   256
#define NEXP  64
#define NGRP  8
#define TOPG  4
#define TOPK  8
#define CAPE  1024
#define RSCALE 2.5f

#define TM    64                 // token rows per expert tile
#define TILES (CAPE / TM)        // 16
#define NC1   32                 // GEMM1 k-chunks (512/16)
#define NC2   16                 // GEMM2 k-chunks (256/16)

// smem map (SB 1024-aligned):
//   [0,      65536): Xh ; reused after GEMM1 as Hh (32 KB @0) + Hl (32 KB @32768)
//   [65536, 131072): Xl
//   [131072,229376): B stages: 3 x 32 KB, each {hi:16 KB, lo:16 KB}
#define SM_XL  65536u
#define SM_B   131072u
#define SM_BYTES (229376 + 1024)

// ---------------- device scratch (static; no allocations allowed) -----------
__device__ int   g_cnt[NEXP];
__device__ int   g_tok[NEXP * CAPE];
__device__ float g_wt[NEXP * CAPE];

// ---------------- helpers ----------------------------------------------------
__device__ __forceinline__ unsigned su32(const void* p) {
    return (unsigned)__cvta_generic_to_shared(p);
}
__device__ __forceinline__ void ldsm4(uint32_t* r, uint32_t a) {
    asm volatile("ldmatrix.sync.aligned.m8n8.x4.shared.b16 {%0,%1,%2,%3}, [%4];"
        : "=r"(r[0]), "=r"(r[1]), "=r"(r[2]), "=r"(r[3]) : "r"(a));
}
__device__ __forceinline__ void mmabf(float* c, const uint32_t* a, const uint32_t* b) {
    asm volatile("mma.sync.aligned.m16n8k16.row.col.f32.bf16.bf16.f32 "
        "{%0,%1,%2,%3}, {%4,%5,%6,%7}, {%8,%9}, {%0,%1,%2,%3};"
        : "+f"(c[0]), "+f"(c[1]), "+f"(c[2]), "+f"(c[3])
        : "r"(a[0]), "r"(a[1]), "r"(a[2]), "r"(a[3]), "r"(b[0]), "r"(b[1]));
}
#define STS128(a, v0, v1, v2, v3) \
    asm volatile("st.shared.v4.b32 [%0], {%1,%2,%3,%4};" \
        :: "r"(a), "r"(v0), "r"(v1), "r"(v2), "r"(v3) : "memory")

// conflict-free XOR swizzles (granule = 16 B)
__device__ __forceinline__ uint32_t xoff(int row, int kq) {   // 1024 B rows (X)
    return (uint32_t)(row * 1024 + (((kq & ~7) | ((kq ^ row) & 7)) << 4));
}
__device__ __forceinline__ uint32_t hoff(int row, int kq) {   // 512 B rows (H)
    return (uint32_t)(row * 512 + (((kq & ~7) | ((kq ^ row) & 7)) << 4));
}
__device__ __forceinline__ uint32_t boff(int n, int kh) {     // 32 B rows (B)
    return (uint32_t)(n * 32 + ((kh ^ ((n >> 2) & 1)) << 4));
}
__device__ __forceinline__ uint32_t pkbf(float a, float b) {
    __nv_bfloat16 h0 = __float2bfloat16(a), h1 = __float2bfloat16(b);
    return (uint32_t)__bfloat16_as_ushort(h0) |
           ((uint32_t)__bfloat16_as_ushort(h1) << 16);
}

// ---------------------------------------------------------------------------
__global__ void k_init() {
    if (threadIdx.x < NEXP) g_cnt[threadIdx.x] = 0;
}

__global__ void k_zero(float* __restrict__ out) {
    ((float4*)out)[blockIdx.x * 256 + threadIdx.x] =
        make_float4(0.f, 0.f, 0.f, 0.f);
}

// ---------------- gating (unchanged, proven) --------------------------------
__global__ void __launch_bounds__(256) k_gate(const float* __restrict__ x,
                                              const float* __restrict__ gw,
                                              const float* __restrict__ gb) {
    __shared__ float wbuf[8 * DIMV];
    __shared__ float sc[8][NEXP];
    __shared__ float sb[8][NEXP];
    __shared__ float gbs[NEXP];

    int tid = threadIdx.x;
    int w = tid >> 5, lane = tid & 31;
    int t = blockIdx.x * 8 + w;

    if (tid < NEXP) gbs[tid] = gb[tid];

    float xr[16];
#pragma unroll
    for (int i = 0; i < 16; i++) xr[i] = x[(size_t)t * DIMV + lane + 32 * i];

    for (int ec = 0; ec < NEXP / 8; ec++) {
        __syncthreads();
#pragma unroll
        for (int q = 0; q < 16; q++) {
            int idx = q * 256 + tid;
            wbuf[idx] = gw[(size_t)(ec * 8) * DIMV + idx];
        }
        __syncthreads();
#pragma unroll
        for (int j = 0; j < 8; j++) {
            float s = 0.f;
#pragma unroll
            for (int i = 0; i < 16; i++) s += xr[i] * wbuf[j * DIMV + lane + 32 * i];
#pragma unroll
            for (int off = 16; off; off >>= 1) s += __shfl_xor_sync(0xffffffffu, s, off);
            if (lane == 0) sc[w][ec * 8 + j] = 1.f / (1.f + __expf(-s));
        }
    }
    __syncthreads();

    if (lane == 0) {
        float* scw = sc[w];
        float* sbw = sb[w];
        float gs[NGRP];
        for (int g = 0; g < NGRP; g++) {
            float m1 = -1e30f, m2 = -1e30f;
            for (int j = 0; j < 8; j++) {
                float v = scw[g * 8 + j] + gbs[g * 8 + j];
                if (v > m1) { m2 = m1; m1 = v; }
                else if (v > m2) { m2 = v; }
            }
            gs[g] = m1 + m2;
        }
        unsigned allowed = 0;
        for (int p = 0; p < TOPG; p++) {
            float best = -1e30f; int bi = 0;
            for (int g = 0; g < NGRP; g++)
                if (!((allowed >> g) & 1) && gs[g] > best) { best = gs[g]; bi = g; }
            allowed |= 1u << bi;
        }
        for (int e = 0; e < NEXP; e++)
            sbw[e] = ((allowed >> (e >> 3)) & 1) ? scw[e] + gbs[e] : -1e30f;
        int idxs[TOPK]; float wsum = 0.f;
        for (int p = 0; p < TOPK; p++) {
            float best = -1e30f; int bi = 0;
            for (int e = 0; e < NEXP; e++)
                if (sbw[e] > best) { best = sbw[e]; bi = e; }
            idxs[p] = bi; sbw[bi] = -1e30f;
            wsum += scw[bi];
        }
        float inv = RSCALE / wsum;
        for (int p = 0; p < TOPK; p++) {
            int e = idxs[p];
            int pos = atomicAdd(&g_cnt[e], 1);
            if (pos < CAPE) {
                g_tok[e * CAPE + pos] = t;
                g_wt[e * CAPE + pos]  = scw[e] * inv;
            }
        }
    }
}

// ---------------- expert FFN: inline-split bf16 hi/lo 3-pass HMMA -----------
__global__ void __launch_bounds__(512, 1)
k_expert_mma(const float* __restrict__ x,  const float* __restrict__ w1,
             const float* __restrict__ w3, const float* __restrict__ w2,
             float* __restrict__ out) {
    extern __shared__ char smraw[];
    char* SB = (char*)(((uintptr_t)smraw + 1023) & ~(uintptr_t)1023);
    __shared__ int   tok_s[TM];
    __shared__ float wt_s[TM];

    int e    = blockIdx.x >> 4;
    int tile = blockIdx.x & (TILES - 1);
    int tid  = threadIdx.x;
    int wid  = tid >> 5, lane = tid & 31;
    int wm = wid & 3, wn = wid >> 2;          // 4 x 4 warp grid

    int n = min(g_cnt[e], CAPE);
    int r0g = tile * TM;
    if (r0g >= n) return;                     // uniform over block
    int nr = min(TM, n - r0g);

    if (tid < TM) {
        int ok = tid < nr;
        tok_s[tid] = ok ? g_tok[e * CAPE + r0g + tid] : 0;
        wt_s[tid]  = ok ? g_wt[e * CAPE + r0g + tid]  : 0.f;
    }
    __syncthreads();

    uint32_t sbase = su32(SB);

    // ---- weight prefetch loaders (fp32 -> registers; thread owns n'=tid) ----
    // GEMM1: n' interleaves w1/w3 columns: m = tid&1, col = tid>>1; k stride 256
    const float* w13base = ((tid & 1) ? w3 : w1) +
                           (size_t)e * 512 * 256 + (tid >> 1);
    auto ldgW1 = [&](int kc, float* r) {
        const float* p = w13base + (size_t)(kc * 16) * 256;
#pragma unroll
        for (int k = 0; k < 16; k++) r[k] = p[k * 256];
    };
    // GEMM2: n' = d = tid; k stride 512
    const float* w2base = w2 + (size_t)e * 256 * 512 + tid;
    auto ldgW2 = [&](int kc, float* r) {
        const float* p = w2base + (size_t)(kc * 16) * 512;
#pragma unroll
        for (int k = 0; k < 16; k++) r[k] = p[k * 512];
    };
    // convert 16 fp32 (k-run of row n'=tid) -> hi/lo granules in stage
    auto stW = [&](const float* r, uint32_t stage) {
#pragma unroll
        for (int kh = 0; kh < 2; kh++) {
            uint32_t H[4], L[4];
#pragma unroll
            for (int q = 0; q < 4; q++) {
                float v0 = r[kh * 8 + q * 2], v1 = r[kh * 8 + q * 2 + 1];
                __nv_bfloat16 h0 = __float2bfloat16(v0);
                __nv_bfloat16 h1 = __float2bfloat16(v1);
                H[q] = (uint32_t)__bfloat16_as_ushort(h0) |
                       ((uint32_t)__bfloat16_as_ushort(h1) << 16);
                L[q] = pkbf(v0 - __bfloat162float(h0), v1 - __bfloat162float(h1));
            }
            uint32_t a = stage + boff(tid, kh);
            STS128(a,         H[0], H[1], H[2], H[3]);
            STS128(a + 16384, L[0], L[1], L[2], L[3]);
        }
    };

    // ---- Prologue: X fp32 -> bf16 hi/lo smem; W1 chunks 0 staged, 1 in regs
#pragma unroll
    for (int it = 0; it < 8; it++) {
        int id = it * 512 + tid;                  // 4096 (row, kq) granule slots
        int row = id >> 6, kq = id & 63;
        const float* src = x + (size_t)tok_s[row] * DIMV + kq * 8;
        float v[8];
        *(float4*)(v)     = *(const float4*)(src);
        *(float4*)(v + 4) = *(const float4*)(src + 4);
        uint32_t H[4], L[4];
#pragma unroll
        for (int q = 0; q < 4; q++) {
            __nv_bfloat16 h0 = __float2bfloat16(v[2 * q]);
            __nv_bfloat16 h1 = __float2bfloat16(v[2 * q + 1]);
            H[q] = (uint32_t)__bfloat16_as_ushort(h0) |
                   ((uint32_t)__bfloat16_as_ushort(h1) << 16);
            L[q] = pkbf(v[2 * q]     - __bfloat162float(h0),
                        v[2 * q + 1] - __bfloat162float(h1));
        }
        uint32_t a = xoff(row, kq);
        STS128(sbase + a,         H[0], H[1], H[2], H[3]);
        STS128(sbase + SM_XL + a, L[0], L[1], L[2], L[3]);
    }

    float rgs[16];
    ldgW1(0, rgs);
    stW(rgs, sbase + SM_B + 0 * 32768u);
    ldgW1(1, rgs);
    __syncthreads();                              // X + B stage0 ready

    // lane decompositions
    int lrow = lane & 7, lm = (lane >> 3) & 1, lkh = lane >> 4;   // A ldsm4
    int bN = ((lane >> 4) & 1) * 8 + (lane & 7);                   // B ldsm4 n-offset
    int bKH = (lane >> 3) & 1;                                     // B k-half

    // ================= GEMM1: [64,512] x W13T -> z (n' interleaved) =========
    float acc[16][4];
#pragma unroll
    for (int j = 0; j < 16; j++)
#pragma unroll
        for (int v = 0; v < 4; v++) acc[j][v] = 0.f;

#pragma unroll 1
    for (int kc = 0; kc < NC1; kc++) {
        // rgs hold W(kc+1); stage (kc+1)%3's old content last read by mma(kc-2)
        if (kc + 1 < NC1) {
            stW(rgs, sbase + SM_B + (uint32_t)((kc + 1) % 3) * 32768u);
            ldgW1(min(kc + 2, NC1 - 1), rgs);
        }
        __syncthreads();

        uint32_t ah[4], al[4];
        {
            int row = wm * 16 + lrow + lm * 8;
            int kq = kc * 2 + lkh;
            uint32_t off = xoff(row, kq);
            ldsm4(ah, sbase + off);
            ldsm4(al, sbase + SM_XL + off);
        }
        uint32_t bb = sbase + SM_B + (uint32_t)(kc % 3) * 32768u;
#pragma unroll
        for (int j2 = 0; j2 < 8; j2++) {
            int nn = wn * 128 + j2 * 16 + bN;
            uint32_t bo = boff(nn, bKH);
            uint32_t bh[4], bl[4];
            ldsm4(bh, bb + bo);
            ldsm4(bl, bb + 16384 + bo);
            mmabf(acc[2 * j2],     ah, bh);
            mmabf(acc[2 * j2],     al, bh);
            mmabf(acc[2 * j2],     ah, bl);
            mmabf(acc[2 * j2 + 1], ah, bh + 2);
            mmabf(acc[2 * j2 + 1], al, bh + 2);
            mmabf(acc[2 * j2 + 1], ah, bl + 2);
        }
    }
    __syncthreads();                              // all X/B reads done

    // ---- Epilogue 1: (z1,z3) in-register -> h bf16 hi/lo in smem -----------
    // Hh @ SB, Hl @ SB+32768 (reusing Xh region)
    {
        int r1 = wm * 16 + (lane >> 2);
        int r2 = r1 + 8;
#pragma unroll
        for (int j = 0; j < 16; j++) {
            float* c = acc[j];
            int cc = wn * 64 + j * 4 + (lane & 3);     // hidden col
            float h1 = (c[0] * c[1]) / (1.f + __expf(-c[0]));
            float h2 = (c[2] * c[3]) / (1.f + __expf(-c[2]));
            __nv_bfloat16 h1h = __float2bfloat16(h1);
            __nv_bfloat16 h2h = __float2bfloat16(h2);
            int kq = cc >> 3, ci = (cc & 7) * 2;
            *(__nv_bfloat16*)(SB + hoff(r1, kq) + ci) = h1h;
            *(__nv_bfloat16*)(SB + hoff(r2, kq) + ci) = h2h;
            *(__nv_bfloat16*)(SB + 32768 + hoff(r1, kq) + ci) =
                __float2bfloat16(h1 - __bfloat162float(h1h));
            *(__nv_bfloat16*)(SB + 32768 + hoff(r2, kq) + ci) =
                __float2bfloat16(h2 - __bfloat162float(h2h));
        }
    }
    // prologue for GEMM2 weight pipeline (B stage0; stage0 last read at kc=30,
    // separated by the loop-tail barrier above)
    ldgW2(0, rgs);
    stW(rgs, sbase + SM_B + 0 * 32768u);
    ldgW2(1, rgs);
    __syncthreads();                              // H + B stage0 visible

    // ================= GEMM2: [64,256] x W2T -> Y [64,512] ==================
    float acc2[16][4];
#pragma unroll
    for (int j = 0; j < 16; j++)
#pragma unroll
        for (int v = 0; v < 4; v++) acc2[j][v] = 0.f;

#pragma unroll 1
    for (int kc = 0; kc < NC2; kc++) {
        if (kc + 1 < NC2) {
            stW(rgs, sbase + SM_B + (uint32_t)((kc + 1) % 3) * 32768u);
            ldgW2(min(kc + 2, NC2 - 1), rgs);
        }
        __syncthreads();

        uint32_t ah[4], al[4];
        {
            int row = wm * 16 + lrow + lm * 8;
            int kq = kc * 2 + lkh;
            uint32_t off = hoff(row, kq);
            ldsm4(ah, sbase + off);
            ldsm4(al, sbase + 32768 + off);
        }
        uint32_t bb = sbase + SM_B + (uint32_t)(kc % 3) * 32768u;
#pragma unroll
        for (int j2 = 0; j2 < 8; j2++) {
            int nn = wn * 128 + j2 * 16 + bN;
            uint32_t bo = boff(nn, bKH);
            uint32_t bh[4], bl[4];
            ldsm4(bh, bb + bo);
            ldsm4(bl, bb + 16384 + bo);
            mmabf(acc2[2 * j2],     ah, bh);
            mmabf(acc2[2 * j2],     al, bh);
            mmabf(acc2[2 * j2],     ah, bl);
            mmabf(acc2[2 * j2 + 1], ah, bh + 2);
            mmabf(acc2[2 * j2 + 1], al, bh + 2);
            mmabf(acc2[2 * j2 + 1], ah, bl + 2);
        }
    }

    // ---- Epilogue 2: scale rows + atomic accumulate into out ---------------
    {
        int r1 = wm * 16 + (lane >> 2);
        int r2 = r1 + 8;
        float w1s = (r1 < nr) ? wt_s[r1] : 0.f;
        float w2s = (r2 < nr) ? wt_s[r2] : 0.f;
        float* o1 = out + (size_t)tok_s[r1] * DIMV;
        float* o2 = out + (size_t)tok_s[r2] * DIMV;
#pragma unroll
        for (int j = 0; j < 16; j++) {
            float* c = acc2[j];
            int d = wn * 128 + j * 8 + (lane & 3) * 2;
            if (r1 < nr) {
                atomicAdd(o1 + d,     c[0] * w1s);
                atomicAdd(o1 + d + 1, c[1] * w1s);
            }
            if (r2 < nr) {
                atomicAdd(o2 + d,     c[2] * w2s);
                atomicAdd(o2 + d + 1, c[3] * w2s);
            }
        }
    }
}

// ---------------------------------------------------------------------------
extern "C" void kernel_launch(void* const* d_in, const int* in_sizes, int n_in,
                              void* d_out, int out_size) {
    const float* x  = (const float*)d_in[0];
    const float* gw = (const float*)d_in[1];
    const float* gb = (const float*)d_in[2];
    const float* w1 = (const float*)d_in[3];
    const float* w3 = (const float*)d_in[4];
    const float* w2 = (const float*)d_in[5];
    float* out = (float*)d_out;

    (void)in_sizes; (void)n_in; (void)out_size;

    cudaFuncSetAttribute(k_expert_mma, cudaFuncAttributeMaxDynamicSharedMemorySize,
                         SM_BYTES);

    k_init<<<1, 64>>>();
    k_zero<<<(T_TOK * DIMV) / 4 / 256, 256>>>(out);
    k_gate<<<T_TOK / 8, 256>>>(x, gw, gb);
    k_expert_mma<<<NEXP * TILES, 512, SM_BYTES>>>(x, w1, w3, w2, out);
}

// round 14
// speedup vs baseline: 1.6491x; 1.0585x over previous
#include <cuda_runtime.h>
#include <cuda_bf16.h>
#include <cstdint>
#include <cstddef>

// Problem constants
#define T_TOK 2048
#define DIMV  512
#define MOE   256
#define NEXP  64
#define NGRP  8
#define TOPG  4
#define TOPK  8
#define CAPE  1024
#define RSCALE 2.5f

#define TM    64                 // token rows per expert tile
#define TILES (CAPE / TM)        // 16
#define NC1   32                 // GEMM1 k-chunks (512/16)
#define NC2   16                 // GEMM2 k-chunks (256/16)

// smem map (SB 1024-aligned):
//   [0,      65536): Xh ; reused after GEMM1 as Hh (32 KB @0) + Hl (32 KB @32768)
//   [65536, 131072): Xl
//   [131072,229376): B stages: 3 x 32 KB, each {hi:16 KB, lo:16 KB}
#define SM_XL  65536u
#define SM_B   131072u
#define SM_BYTES (229376 + 1024)

// ---------------- device scratch (static; no allocations allowed) -----------
__device__ int   g_cnt[NEXP];
__device__ int   g_tok[NEXP * CAPE];
__device__ float g_wt[NEXP * CAPE];

// ---------------- helpers ----------------------------------------------------
__device__ __forceinline__ unsigned su32(const void* p) {
    return (unsigned)__cvta_generic_to_shared(p);
}
__device__ __forceinline__ void ldsm4(uint32_t* r, uint32_t a) {
    asm volatile("ldmatrix.sync.aligned.m8n8.x4.shared.b16 {%0,%1,%2,%3}, [%4];"
        : "=r"(r[0]), "=r"(r[1]), "=r"(r[2]), "=r"(r[3]) : "r"(a));
}
__device__ __forceinline__ void mmabf(float* c, const uint32_t* a, const uint32_t* b) {
    asm volatile("mma.sync.aligned.m16n8k16.row.col.f32.bf16.bf16.f32 "
        "{%0,%1,%2,%3}, {%4,%5,%6,%7}, {%8,%9}, {%0,%1,%2,%3};"
        : "+f"(c[0]), "+f"(c[1]), "+f"(c[2]), "+f"(c[3])
        : "r"(a[0]), "r"(a[1]), "r"(a[2]), "r"(a[3]), "r"(b[0]), "r"(b[1]));
}
#define STS128(a, v0, v1, v2, v3) \
    asm volatile("st.shared.v4.b32 [%0], {%1,%2,%3,%4};" \
        :: "r"(a), "r"(v0), "r"(v1), "r"(v2), "r"(v3) : "memory")

// conflict-free XOR swizzles (granule = 16 B)
__device__ __forceinline__ uint32_t xoff(int row, int kq) {   // 1024 B rows (X)
    return (uint32_t)(row * 1024 + (((kq & ~7) | ((kq ^ row) & 7)) << 4));
}
__device__ __forceinline__ uint32_t hoff(int row, int kq) {   // 512 B rows (H)
    return (uint32_t)(row * 512 + (((kq & ~7) | ((kq ^ row) & 7)) << 4));
}
__device__ __forceinline__ uint32_t boff(int n, int kh) {     // 32 B rows (B)
    return (uint32_t)(n * 32 + ((kh ^ ((n >> 2) & 1)) << 4));
}
__device__ __forceinline__ uint32_t pkbf(float a, float b) {
    __nv_bfloat16 h0 = __float2bfloat16(a), h1 = __float2bfloat16(b);
    return (uint32_t)__bfloat16_as_ushort(h0) |
           ((uint32_t)__bfloat16_as_ushort(h1) << 16);
}

// ---------------------------------------------------------------------------
__global__ void k_init() {
    if (threadIdx.x < NEXP) g_cnt[threadIdx.x] = 0;
}

__global__ void k_zero(float* __restrict__ out) {
    ((float4*)out)[blockIdx.x * 256 + threadIdx.x] =
        make_float4(0.f, 0.f, 0.f, 0.f);
}

// ---------------- gating (unchanged, proven) --------------------------------
__global__ void __launch_bounds__(256) k_gate(const float* __restrict__ x,
                                              const float* __restrict__ gw,
                                              const float* __restrict__ gb) {
    __shared__ float wbuf[8 * DIMV];
    __shared__ float sc[8][NEXP];
    __shared__ float sb[8][NEXP];
    __shared__ float gbs[NEXP];

    int tid = threadIdx.x;
    int w = tid >> 5, lane = tid & 31;
    int t = blockIdx.x * 8 + w;

    if (tid < NEXP) gbs[tid] = gb[tid];

    float xr[16];
#pragma unroll
    for (int i = 0; i < 16; i++) xr[i] = x[(size_t)t * DIMV + lane + 32 * i];

    for (int ec = 0; ec < NEXP / 8; ec++) {
        __syncthreads();
#pragma unroll
        for (int q = 0; q < 16; q++) {
            int idx = q * 256 + tid;
            wbuf[idx] = gw[(size_t)(ec * 8) * DIMV + idx];
        }
        __syncthreads();
#pragma unroll
        for (int j = 0; j < 8; j++) {
            float s = 0.f;
#pragma unroll
            for (int i = 0; i < 16; i++) s += xr[i] * wbuf[j * DIMV + lane + 32 * i];
#pragma unroll
            for (int off = 16; off; off >>= 1) s += __shfl_xor_sync(0xffffffffu, s, off);
            if (lane == 0) sc[w][ec * 8 + j] = 1.f / (1.f + __expf(-s));
        }
    }
    __syncthreads();

    if (lane == 0) {
        float* scw = sc[w];
        float* sbw = sb[w];
        float gs[NGRP];
        for (int g = 0; g < NGRP; g++) {
            float m1 = -1e30f, m2 = -1e30f;
            for (int j = 0; j < 8; j++) {
                float v = scw[g * 8 + j] + gbs[g * 8 + j];
                if (v > m1) { m2 = m1; m1 = v; }
                else if (v > m2) { m2 = v; }
            }
            gs[g] = m1 + m2;
        }
        unsigned allowed = 0;
        for (int p = 0; p < TOPG; p++) {
            float best = -1e30f; int bi = 0;
            for (int g = 0; g < NGRP; g++)
                if (!((allowed >> g) & 1) && gs[g] > best) { best = gs[g]; bi = g; }
            allowed |= 1u << bi;
        }
        for (int e = 0; e < NEXP; e++)
            sbw[e] = ((allowed >> (e >> 3)) & 1) ? scw[e] + gbs[e] : -1e30f;
        int idxs[TOPK]; float wsum = 0.f;
        for (int p = 0; p < TOPK; p++) {
            float best = -1e30f; int bi = 0;
            for (int e = 0; e < NEXP; e++)
                if (sbw[e] > best) { best = sbw[e]; bi = e; }
            idxs[p] = bi; sbw[bi] = -1e30f;
            wsum += scw[bi];
        }
        float inv = RSCALE / wsum;
        for (int p = 0; p < TOPK; p++) {
            int e = idxs[p];
            int pos = atomicAdd(&g_cnt[e], 1);
            if (pos < CAPE) {
                g_tok[e * CAPE + pos] = t;
                g_wt[e * CAPE + pos]  = scw[e] * inv;
            }
        }
    }
}

// ---------------- expert FFN: inline-split bf16 hi/lo 3-pass HMMA -----------
// Warp grid 2(m) x 8(n): warp tile = 32 rows x 64 cols -> minimal ldsm traffic
__global__ void __launch_bounds__(512, 1)
k_expert_mma(const float* __restrict__ x,  const float* __restrict__ w1,
             const float* __restrict__ w3, const float* __restrict__ w2,
             float* __restrict__ out) {
    extern __shared__ char smraw[];
    char* SB = (char*)(((uintptr_t)smraw + 1023) & ~(uintptr_t)1023);
    __shared__ int   tok_s[TM];
    __shared__ float wt_s[TM];

    int e    = blockIdx.x >> 4;
    int tile = blockIdx.x & (TILES - 1);
    int tid  = threadIdx.x;
    int wid  = tid >> 5, lane = tid & 31;
    int wm = wid & 1, wn = wid >> 1;          // 2 x 8 warp grid

    int n = min(g_cnt[e], CAPE);
    int r0g = tile * TM;
    if (r0g >= n) return;                     // uniform over block
    int nr = min(TM, n - r0g);

    if (tid < TM) {
        int ok = tid < nr;
        tok_s[tid] = ok ? g_tok[e * CAPE + r0g + tid] : 0;
        wt_s[tid]  = ok ? g_wt[e * CAPE + r0g + tid]  : 0.f;
    }
    __syncthreads();

    uint32_t sbase = su32(SB);

    // ---- weight prefetch loaders (fp32 -> registers; thread owns n'=tid) ----
    const float* w13base = ((tid & 1) ? w3 : w1) +
                           (size_t)e * 512 * 256 + (tid >> 1);
    auto ldgW1 = [&](int kc, float* r) {
        const float* p = w13base + (size_t)(kc * 16) * 256;
#pragma unroll
        for (int k = 0; k < 16; k++) r[k] = p[k * 256];
    };
    const float* w2base = w2 + (size_t)e * 256 * 512 + tid;
    auto ldgW2 = [&](int kc, float* r) {
        const float* p = w2base + (size_t)(kc * 16) * 512;
#pragma unroll
        for (int k = 0; k < 16; k++) r[k] = p[k * 512];
    };
    auto stW = [&](const float* r, uint32_t stage) {
#pragma unroll
        for (int kh = 0; kh < 2; kh++) {
            uint32_t H[4], L[4];
#pragma unroll
            for (int q = 0; q < 4; q++) {
                float v0 = r[kh * 8 + q * 2], v1 = r[kh * 8 + q * 2 + 1];
                __nv_bfloat16 h0 = __float2bfloat16(v0);
                __nv_bfloat16 h1 = __float2bfloat16(v1);
                H[q] = (uint32_t)__bfloat16_as_ushort(h0) |
                       ((uint32_t)__bfloat16_as_ushort(h1) << 16);
                L[q] = pkbf(v0 - __bfloat162float(h0), v1 - __bfloat162float(h1));
            }
            uint32_t a = stage + boff(tid, kh);
            STS128(a,         H[0], H[1], H[2], H[3]);
            STS128(a + 16384, L[0], L[1], L[2], L[3]);
        }
    };

    // ---- Prologue: X fp32 -> bf16 hi/lo smem; W1 chunk 0 staged, 1 in regs --
#pragma unroll
    for (int it = 0; it < 8; it++) {
        int id = it * 512 + tid;                  // 4096 (row, kq) granule slots
        int row = id >> 6, kq = id & 63;
        const float* src = x + (size_t)tok_s[row] * DIMV + kq * 8;
        float v[8];
        *(float4*)(v)     = *(const float4*)(src);
        *(float4*)(v + 4) = *(const float4*)(src + 4);
        uint32_t H[4], L[4];
#pragma unroll
        for (int q = 0; q < 4; q++) {
            __nv_bfloat16 h0 = __float2bfloat16(v[2 * q]);
            __nv_bfloat16 h1 = __float2bfloat16(v[2 * q + 1]);
            H[q] = (uint32_t)__bfloat16_as_ushort(h0) |
                   ((uint32_t)__bfloat16_as_ushort(h1) << 16);
            L[q] = pkbf(v[2 * q]     - __bfloat162float(h0),
                        v[2 * q + 1] - __bfloat162float(h1));
        }
        uint32_t a = xoff(row, kq);
        STS128(sbase + a,         H[0], H[1], H[2], H[3]);
        STS128(sbase + SM_XL + a, L[0], L[1], L[2], L[3]);
    }

    float rgs[16];
    ldgW1(0, rgs);
    stW(rgs, sbase + SM_B + 0 * 32768u);
    ldgW1(1, rgs);
    __syncthreads();                              // X + B stage0 ready

    // lane decompositions
    int lrow = lane & 7, lm = (lane >> 3) & 1, lkh = lane >> 4;   // A ldsm4
    int bN = ((lane >> 4) & 1) * 8 + (lane & 7);                   // B ldsm4 n-offset
    int bKH = (lane >> 3) & 1;                                     // B k-half

    // ================= GEMM1: [64,512] x W13T -> z (n' interleaved) =========
    float acc[2][8][4];
#pragma unroll
    for (int mt = 0; mt < 2; mt++)
#pragma unroll
        for (int j = 0; j < 8; j++)
#pragma unroll
            for (int v = 0; v < 4; v++) acc[mt][j][v] = 0.f;

#pragma unroll 1
    for (int kc = 0; kc < NC1; kc++) {
        // rgs hold W(kc+1); stage (kc+1)%3's old content last read by mma(kc-2)
        if (kc + 1 < NC1) {
            stW(rgs, sbase + SM_B + (uint32_t)((kc + 1) % 3) * 32768u);
            ldgW1(min(kc + 2, NC1 - 1), rgs);
        }
        __syncthreads();

        uint32_t ah[2][4], al[2][4];
#pragma unroll
        for (int mt = 0; mt < 2; mt++) {
            int row = wm * 32 + mt * 16 + lrow + lm * 8;
            int kq = kc * 2 + lkh;
            uint32_t off = xoff(row, kq);
            ldsm4(ah[mt], sbase + off);
            ldsm4(al[mt], sbase + SM_XL + off);
        }
        uint32_t bb = sbase + SM_B + (uint32_t)(kc % 3) * 32768u;
#pragma unroll
        for (int j2 = 0; j2 < 4; j2++) {
            int nn = wn * 64 + j2 * 16 + bN;
            uint32_t bo = boff(nn, bKH);
            uint32_t bh[4], bl[4];
            ldsm4(bh, bb + bo);
            ldsm4(bl, bb + 16384 + bo);
#pragma unroll
            for (int mt = 0; mt < 2; mt++) {
                mmabf(acc[mt][2 * j2],     ah[mt], bh);
                mmabf(acc[mt][2 * j2],     al[mt], bh);
                mmabf(acc[mt][2 * j2],     ah[mt], bl);
                mmabf(acc[mt][2 * j2 + 1], ah[mt], bh + 2);
                mmabf(acc[mt][2 * j2 + 1], al[mt], bh + 2);
                mmabf(acc[mt][2 * j2 + 1], ah[mt], bl + 2);
            }
        }
    }
    __syncthreads();                              // all X/B reads done

    // ---- Epilogue 1: (z1,z3) in-register -> h bf16 hi/lo in smem -----------
    // Hh @ SB, Hl @ SB+32768 (reusing Xh region)
#pragma unroll
    for (int mt = 0; mt < 2; mt++) {
        int r1 = wm * 32 + mt * 16 + (lane >> 2);
        int r2 = r1 + 8;
#pragma unroll
        for (int j = 0; j < 8; j++) {
            float* c = acc[mt][j];
            int cc = wn * 32 + j * 4 + (lane & 3);     // hidden col
            float h1 = (c[0] * c[1]) / (1.f + __expf(-c[0]));
            float h2 = (c[2] * c[3]) / (1.f + __expf(-c[2]));
            __nv_bfloat16 h1h = __float2bfloat16(h1);
            __nv_bfloat16 h2h = __float2bfloat16(h2);
            int kq = cc >> 3, ci = (cc & 7) * 2;
            *(__nv_bfloat16*)(SB + hoff(r1, kq) + ci) = h1h;
            *(__nv_bfloat16*)(SB + hoff(r2, kq) + ci) = h2h;
            *(__nv_bfloat16*)(SB + 32768 + hoff(r1, kq) + ci) =
                __float2bfloat16(h1 - __bfloat162float(h1h));
            *(__nv_bfloat16*)(SB + 32768 + hoff(r2, kq) + ci) =
                __float2bfloat16(h2 - __bfloat162float(h2h));
        }
    }
    // prologue for GEMM2 weight pipeline (stage0 last read at kc=30; separated
    // by the loop-tail barrier above)
    ldgW2(0, rgs);
    stW(rgs, sbase + SM_B + 0 * 32768u);
    ldgW2(1, rgs);
    __syncthreads();                              // H + B stage0 visible

    // ================= GEMM2: [64,256] x W2T -> Y [64,512] ==================
    float acc2[2][8][4];
#pragma unroll
    for (int mt = 0; mt < 2; mt++)
#pragma unroll
        for (int j = 0; j < 8; j++)
#pragma unroll
            for (int v = 0; v < 4; v++) acc2[mt][j][v] = 0.f;

#pragma unroll 1
    for (int kc = 0; kc < NC2; kc++) {
        if (kc + 1 < NC2) {
            stW(rgs, sbase + SM_B + (uint32_t)((kc + 1) % 3) * 32768u);
            ldgW2(min(kc + 2, NC2 - 1), rgs);
        }
        __syncthreads();

        uint32_t ah[2][4], al[2][4];
#pragma unroll
        for (int mt = 0; mt < 2; mt++) {
            int row = wm * 32 + mt * 16 + lrow + lm * 8;
            int kq = kc * 2 + lkh;
            uint32_t off = hoff(row, kq);
            ldsm4(ah[mt], sbase + off);
            ldsm4(al[mt], sbase + 32768 + off);
        }
        uint32_t bb = sbase + SM_B + (uint32_t)(kc % 3) * 32768u;
#pragma unroll
        for (int j2 = 0; j2 < 4; j2++) {
            int nn = wn * 64 + j2 * 16 + bN;
            uint32_t bo = boff(nn, bKH);
            uint32_t bh[4], bl[4];
            ldsm4(bh, bb + bo);
            ldsm4(bl, bb + 16384 + bo);
#pragma unroll
            for (int mt = 0; mt < 2; mt++) {
                mmabf(acc2[mt][2 * j2],     ah[mt], bh);
                mmabf(acc2[mt][2 * j2],     al[mt], bh);
                mmabf(acc2[mt][2 * j2],     ah[mt], bl);
                mmabf(acc2[mt][2 * j2 + 1], ah[mt], bh + 2);
                mmabf(acc2[mt][2 * j2 + 1], al[mt], bh + 2);
                mmabf(acc2[mt][2 * j2 + 1], ah[mt], bl + 2);
            }
        }
    }

    // ---- Epilogue 2: scale rows + atomic accumulate into out ---------------
#pragma unroll
    for (int mt = 0; mt < 2; mt++) {
        int r1 = wm * 32 + mt * 16 + (lane >> 2);
        int r2 = r1 + 8;
        float w1s = (r1 < nr) ? wt_s[r1] : 0.f;
        float w2s = (r2 < nr) ? wt_s[r2] : 0.f;
        float* o1 = out + (size_t)tok_s[r1] * DIMV;
        float* o2 = out + (size_t)tok_s[r2] * DIMV;
#pragma unroll
        for (int j = 0; j < 8; j++) {
            float* c = acc2[mt][j];
            int d = wn * 64 + j * 8 + (lane & 3) * 2;
            if (r1 < nr) {
                atomicAdd(o1 + d,     c[0] * w1s);
                atomicAdd(o1 + d + 1, c[1] * w1s);
            }
            if (r2 < nr) {
                atomicAdd(o2 + d,     c[2] * w2s);
                atomicAdd(o2 + d + 1, c[3] * w2s);
            }
        }
    }
}

// ---------------------------------------------------------------------------
extern "C" void kernel_launch(void* const* d_in, const int* in_sizes, int n_in,
                              void* d_out, int out_size) {
    const float* x  = (const float*)d_in[0];
    const float* gw = (const float*)d_in[1];
    const float* gb = (const float*)d_in[2];
    const float* w1 = (const float*)d_in[3];
    const float* w3 = (const float*)d_in[4];
    const float* w2 = (const float*)d_in[5];
    float* out = (float*)d_out;

    (void)in_sizes; (void)n_in; (void)out_size;

    cudaFuncSetAttribute(k_expert_mma, cudaFuncAttributeMaxDynamicSharedMemorySize,
                         SM_BYTES);

    k_init<<<1, 64>>>();
    k_zero<<<(T_TOK * DIMV) / 4 / 256, 256>>>(out);
    k_gate<<<T_TOK / 8, 256>>>(x, gw, gb);
    k_expert_mma<<<NEXP * TILES, 512, SM_BYTES>>>(x, w1, w3, w2, out);
}